// round 3
// baseline (speedup 1.0000x reference)
#include <cuda_runtime.h>

// GMM EM on GB300. B=8, N=80000, K=5, F=20, 5 iterations + final E-step.
// Inputs:  d_in[0]=data [B,N,F], d_in[1]=means [B,K,F], d_in[2]=variance [B,K,F], d_in[3]=prior [B,K]
// Output:  concat( ll [B,N,K], post [B,N,K], means [B,K,F], var [B,K,F], pi [B,K] ) fp32

#define Bn 8
#define Nn 80000
#define Kn 5
#define Fn 20
#define NITER 5
#define TILE 256
#define XSTRIDE 257          // pad for conflict-free smem transpose
#define NTILES ((Nn + TILE - 1) / TILE)   // 313
#define GRIDX 74

// Per-(b): Sx[k][f] at k*21+f (f==20 column is the constant-1 feature -> Sx == cluster size S),
//          Sxx[k][f] at 105 + k*21+f.
__device__ float g_acc[Bn * 210];

// Per-(b,k) E-step params, padded to 44 floats (16B aligned):
// [2f]=-0.5/ (var+eps) ; [2f+1]=mu/(var+eps) ; [40]=C = log(pi) - 0.5*sum log(2pi var) - 0.5*sum mu^2/(var+eps)
__device__ float4 g_params4[Bn * Kn * 11];

__device__ __forceinline__ void write_params(int b, int k, float C_base,
                                             const float* mu, const float* var) {
    float* gp = reinterpret_cast<float*>(g_params4) + (b * Kn + k) * 44;
    float C = C_base;
#pragma unroll
    for (int f = 0; f < Fn; f++) {
        float v = var[f];
        float m = mu[f];
        float ic = 1.0f / (v + 1e-6f);
        C += -0.5f * logf(6.283185307179586f * v) - 0.5f * ic * m * m;
        gp[2 * f]     = -0.5f * ic;
        gp[2 * f + 1] = ic * m;
    }
    gp[40] = C;
}

// ---------------------------------------------------------------- init
__global__ void init_kernel(const float* __restrict__ means,
                            const float* __restrict__ var,
                            const float* __restrict__ pri) {
    int tid = threadIdx.x;
    if (tid < Bn * Kn) {
        int b = tid / Kn, k = tid - b * Kn;
        float mu[Fn], vv[Fn];
#pragma unroll
        for (int f = 0; f < Fn; f++) {
            mu[f] = means[(b * Kn + k) * Fn + f];
            vv[f] = var[(b * Kn + k) * Fn + f];
        }
        write_params(b, k, logf(pri[b * Kn + k]), mu, vv);
    }
    for (int i = tid; i < Bn * 210; i += blockDim.x) g_acc[i] = 0.0f;
}

// ---------------------------------------------------------------- E-step core (shared by accum + output kernels)
struct EStepSmem {
    float4 AB[Kn][10];
    float  C[Kn];
};

__device__ __forceinline__ void load_params_smem(EStepSmem* sp, int b, int tid) {
    if (tid < Kn * 11) {
        int k = tid / 11, q = tid - k * 11;
        float4 v = g_params4[(b * Kn + k) * 11 + q];
        if (q < 10) sp->AB[k][q] = v;
        else        sp->C[k] = v.x;
    }
}

__device__ __forceinline__ void loglik_softmax(const EStepSmem* sp, const float* x,
                                               float* l, float* p) {
#pragma unroll
    for (int k = 0; k < Kn; k++) {
        float acc = sp->C[k];
#pragma unroll
        for (int j = 0; j < 10; j++) {
            float4 v = sp->AB[k][j];
            float xa = x[2 * j], xb = x[2 * j + 1];
            acc = fmaf(fmaf(v.x, xa, v.y), xa, acc);   // A*x^2 + B*x = x*(A*x+B)
            acc = fmaf(fmaf(v.z, xb, v.w), xb, acc);
        }
        l[k] = acc;
    }
    float m = l[0];
#pragma unroll
    for (int k = 1; k < Kn; k++) m = fmaxf(m, l[k]);
    float s = 0.0f;
#pragma unroll
    for (int k = 0; k < Kn; k++) { p[k] = __expf(l[k] - m); s += p[k]; }
    float inv = __fdividef(1.0f, s);
#pragma unroll
    for (int k = 0; k < Kn; k++) p[k] *= inv;
}

// ---------------------------------------------------------------- accumulate (E-step + partial M-step sums)
__launch_bounds__(TILE)
__global__ void accum_kernel(const float* __restrict__ data) {
    __shared__ EStepSmem sp;
    __shared__ float  sX[21 * XSTRIDE];      // [f][t] transposed tile, f=20 row is all-ones
    __shared__ float4 sPv[TILE * 2];         // posteriors packed [t][8] floats

    const int tid  = threadIdx.x;
    const int b    = blockIdx.y;
    const int wid  = tid >> 5;
    const int lane = tid & 31;
    const int fidx = (lane < 21) ? lane : 20;

    load_params_smem(&sp, b, tid);

    float Sx[Kn]  = {0.f, 0.f, 0.f, 0.f, 0.f};
    float Sxx[Kn] = {0.f, 0.f, 0.f, 0.f, 0.f};

    for (int tile = blockIdx.x; tile < NTILES; tile += GRIDX) {
        const int base   = tile * TILE;
        const int nvalid = min(TILE, Nn - base);

        __syncthreads();   // smem safe to overwrite (params loaded / prev phase2 done)

        // -------- phase 1: per-thread point -> posteriors + staged tile
        if (tid < nvalid) {
            const float4* xp =
                reinterpret_cast<const float4*>(data + ((size_t)b * Nn + base + tid) * Fn);
            float4 xv4[5];
#pragma unroll
            for (int j = 0; j < 5; j++) xv4[j] = __ldg(xp + j);
            float* x = reinterpret_cast<float*>(xv4);

#pragma unroll
            for (int f = 0; f < Fn; f++) sX[f * XSTRIDE + tid] = x[f];
            sX[20 * XSTRIDE + tid] = 1.0f;

            float l[Kn], p[Kn];
            loglik_softmax(&sp, x, l, p);

            sPv[tid * 2] = make_float4(p[0], p[1], p[2], p[3]);
            reinterpret_cast<float*>(sPv)[tid * 8 + 4] = p[4];
        }
        __syncthreads();

        // -------- phase 2: warp owns 32 points, lane owns feature f
        const int t0w = wid * 32;
        int rem = nvalid - t0w;
        int cnt = rem < 0 ? 0 : (rem > 32 ? 32 : rem);
        const float* xrow  = &sX[fidx * XSTRIDE + t0w];
        const float* pbase = reinterpret_cast<const float*>(sPv) + t0w * 8;

        if (cnt == 32) {
#pragma unroll
            for (int i = 0; i < 32; i++) {
                float  xv = xrow[i];
                float4 pv = *reinterpret_cast<const float4*>(pbase + i * 8);
                float  p4 = pbase[i * 8 + 4];
                float px;
                px = pv.x * xv; Sx[0] += px; Sxx[0] = fmaf(px, xv, Sxx[0]);
                px = pv.y * xv; Sx[1] += px; Sxx[1] = fmaf(px, xv, Sxx[1]);
                px = pv.z * xv; Sx[2] += px; Sxx[2] = fmaf(px, xv, Sxx[2]);
                px = pv.w * xv; Sx[3] += px; Sxx[3] = fmaf(px, xv, Sxx[3]);
                px = p4   * xv; Sx[4] += px; Sxx[4] = fmaf(px, xv, Sxx[4]);
            }
        } else {
            for (int i = 0; i < cnt; i++) {
                float  xv = xrow[i];
                float4 pv = *reinterpret_cast<const float4*>(pbase + i * 8);
                float  p4 = pbase[i * 8 + 4];
                float px;
                px = pv.x * xv; Sx[0] += px; Sxx[0] = fmaf(px, xv, Sxx[0]);
                px = pv.y * xv; Sx[1] += px; Sxx[1] = fmaf(px, xv, Sxx[1]);
                px = pv.z * xv; Sx[2] += px; Sxx[2] = fmaf(px, xv, Sxx[2]);
                px = pv.w * xv; Sx[3] += px; Sxx[3] = fmaf(px, xv, Sxx[3]);
                px = p4   * xv; Sx[4] += px; Sxx[4] = fmaf(px, xv, Sxx[4]);
            }
        }
    }

    // -------- block reduction + one atomicAdd per entry
    __syncthreads();
    float* sred = sX;                       // reuse: 8 warps * 210 floats
    if (lane < 21) {
#pragma unroll
        for (int k = 0; k < Kn; k++) sred[wid * 210 + k * 21 + lane]       = Sx[k];
#pragma unroll
        for (int k = 0; k < Kn; k++) sred[wid * 210 + 105 + k * 21 + lane] = Sxx[k];
    }
    __syncthreads();
    if (tid < 210) {
        float v = 0.0f;
#pragma unroll
        for (int w = 0; w < 8; w++) v += sred[w * 210 + tid];
        atomicAdd(&g_acc[b * 210 + tid], v);
    }
}

// ---------------------------------------------------------------- M-step finalize (+ param refresh, + output on last iter)
__global__ void finalize_kernel(int is_last, float* __restrict__ out_means,
                                float* __restrict__ out_var, float* __restrict__ out_pi) {
    int tid = threadIdx.x;
    __shared__ float sS[Bn * Kn];
    if (tid < Bn * Kn) {
        int b = tid / Kn, k = tid - b * Kn;
        sS[tid] = g_acc[b * 210 + k * 21 + 20];
    }
    __syncthreads();
    if (tid < Bn * Kn) {
        int b = tid / Kn, k = tid - b * Kn;
        float S = sS[tid];
        float sum = sS[b * Kn + 0] + sS[b * Kn + 1] + sS[b * Kn + 2] +
                    sS[b * Kn + 3] + sS[b * Kn + 4];
        // pi = (S/N) / max(sum|S|/N, 1e-12) == S / max(sum, N*1e-12)
        float pi = S / fmaxf(sum, (float)Nn * 1e-12f);
        float dS = S + 1e-7f;
        float invdS = 1.0f / dS;

        float mu[Fn], vv[Fn];
#pragma unroll
        for (int f = 0; f < Fn; f++) {
            float sx  = g_acc[b * 210 + k * 21 + f];
            float sxx = g_acc[b * 210 + 105 + k * 21 + f];
            float m = sx * invdS;
            float v = (sxx - 2.0f * m * sx + m * m * S) * invdS + 1e-6f;  // var + EPS_VAR
            mu[f] = m;
            vv[f] = v;
        }
        write_params(b, k, logf(pi), mu, vv);
        if (is_last) {
#pragma unroll
            for (int f = 0; f < Fn; f++) {
                out_means[(b * Kn + k) * Fn + f] = mu[f];
                out_var[(b * Kn + k) * Fn + f]   = vv[f];
            }
            out_pi[b * Kn + k] = pi;
        }
    }
    __syncthreads();
    for (int i = tid; i < Bn * 210; i += blockDim.x) g_acc[i] = 0.0f;
}

// ---------------------------------------------------------------- final E-step: write ll + post [B,N,K]
__launch_bounds__(TILE)
__global__ void estep_out_kernel(const float* __restrict__ data,
                                 float* __restrict__ out_ll,
                                 float* __restrict__ out_post) {
    __shared__ EStepSmem sp;
    const int tid = threadIdx.x;
    const int b   = blockIdx.y;
    load_params_smem(&sp, b, tid);
    __syncthreads();

    int n = blockIdx.x * TILE + tid;
    if (n < Nn) {
        const float4* xp =
            reinterpret_cast<const float4*>(data + ((size_t)b * Nn + n) * Fn);
        float4 xv4[5];
#pragma unroll
        for (int j = 0; j < 5; j++) xv4[j] = __ldg(xp + j);
        float* x = reinterpret_cast<float*>(xv4);

        float l[Kn], p[Kn];
        loglik_softmax(&sp, x, l, p);

        size_t o = ((size_t)b * Nn + n) * Kn;
#pragma unroll
        for (int k = 0; k < Kn; k++) out_ll[o + k] = l[k];
#pragma unroll
        for (int k = 0; k < Kn; k++) out_post[o + k] = p[k];
    }
}

// ---------------------------------------------------------------- launch
extern "C" void kernel_launch(void* const* d_in, const int* in_sizes, int n_in,
                              void* d_out, int out_size) {
    const float* data  = (const float*)d_in[0];
    const float* means = (const float*)d_in[1];
    const float* var   = (const float*)d_in[2];
    const float* pri   = (const float*)d_in[3];

    float* out = (float*)d_out;
    size_t NK = (size_t)Bn * Nn * Kn;                 // 3,200,000
    float* out_ll    = out;
    float* out_post  = out + NK;
    float* out_means = out + 2 * NK;
    float* out_var   = out_means + Bn * Kn * Fn;      // +800
    float* out_pi    = out_var   + Bn * Kn * Fn;      // +800

    init_kernel<<<1, 256>>>(means, var, pri);
    for (int it = 0; it < NITER; it++) {
        accum_kernel<<<dim3(GRIDX, Bn), TILE>>>(data);
        finalize_kernel<<<1, 256>>>(it == NITER - 1 ? 1 : 0, out_means, out_var, out_pi);
    }
    estep_out_kernel<<<dim3(NTILES, Bn), TILE>>>(data, out_ll, out_post);
}

// round 4
// speedup vs baseline: 1.1244x; 1.1244x over previous
#include <cuda_runtime.h>

typedef unsigned long long ull;

// GMM EM on GB300. B=8, N=80000, K=5, F=20, 5 iterations + final E-step.
// Inputs:  d_in[0]=data [B,N,F], d_in[1]=means [B,K,F], d_in[2]=variance [B,K,F], d_in[3]=prior [B,K]
// Output:  concat( ll [B,N,K], post [B,N,K], means [B,K,F], var [B,K,F], pi [B,K] ) fp32

#define Bn 8
#define Nn 80000
#define Kn 5
#define Fn 20
#define NITER 5
#define TILE 256
#define NTILES ((Nn + TILE - 1) / TILE)   // 313
#define GRIDX 148

// Per-(b): Sx[k][f] at k*21+f (f==20 is the constant-1 feature -> Sx == cluster size S),
//          Sxx[k][f] at 105 + k*21+f.
__device__ float g_acc[Bn * 210];

// Per-(b,k) E-step params, 44 floats (11 float4):
// float4 j (j=0..9): {A_{2j}, A_{2j+1}, B_{2j}, B_{2j+1}} with A_f = -0.5/(var+eps), B_f = mu/(var+eps)
// [40] = C = log(pi) - 0.5*sum log(2pi var) - 0.5*sum mu^2/(var+eps)
__device__ float4 g_params4[Bn * Kn * 11];

// ---------------------------------------------------------------- f32x2 helpers
__device__ __forceinline__ ull pk2(float lo, float hi) {
    ull r; asm("mov.b64 %0,{%1,%2};" : "=l"(r) : "f"(lo), "f"(hi)); return r;
}
__device__ __forceinline__ void up2(ull v, float& lo, float& hi) {
    asm("mov.b64 {%0,%1},%2;" : "=f"(lo), "=f"(hi) : "l"(v));
}
__device__ __forceinline__ ull fma2(ull a, ull b, ull c) {
    ull d; asm("fma.rn.f32x2 %0,%1,%2,%3;" : "=l"(d) : "l"(a), "l"(b), "l"(c)); return d;
}
__device__ __forceinline__ ull mul2(ull a, ull b) {
    ull d; asm("mul.rn.f32x2 %0,%1,%2;" : "=l"(d) : "l"(a), "l"(b)); return d;
}

// ---------------------------------------------------------------- params writer
__device__ __forceinline__ void write_params(int b, int k, float C_base,
                                             const float* mu, const float* var) {
    float* gp = reinterpret_cast<float*>(g_params4) + (b * Kn + k) * 44;
    float C = C_base;
    float A[Fn], Bc[Fn];
#pragma unroll
    for (int f = 0; f < Fn; f++) {
        float v = var[f];
        float m = mu[f];
        float ic = 1.0f / (v + 1e-6f);
        C += -0.5f * logf(6.283185307179586f * v) - 0.5f * ic * m * m;
        A[f]  = -0.5f * ic;
        Bc[f] = ic * m;
    }
#pragma unroll
    for (int j = 0; j < 10; j++) {
        gp[4 * j]     = A[2 * j];
        gp[4 * j + 1] = A[2 * j + 1];
        gp[4 * j + 2] = Bc[2 * j];
        gp[4 * j + 3] = Bc[2 * j + 1];
    }
    gp[40] = C;
}

// ---------------------------------------------------------------- init
__global__ void init_kernel(const float* __restrict__ means,
                            const float* __restrict__ var,
                            const float* __restrict__ pri) {
    int tid = threadIdx.x;
    if (tid < Bn * Kn) {
        int b = tid / Kn, k = tid - b * Kn;
        float mu[Fn], vv[Fn];
#pragma unroll
        for (int f = 0; f < Fn; f++) {
            mu[f] = means[(b * Kn + k) * Fn + f];
            vv[f] = var[(b * Kn + k) * Fn + f];
        }
        write_params(b, k, logf(pri[b * Kn + k]), mu, vv);
    }
    for (int i = tid; i < Bn * 210; i += blockDim.x) g_acc[i] = 0.0f;
}

// ---------------------------------------------------------------- E-step core
struct EStepSmem {
    ulonglong2 AB[Kn][10];   // .x = packed(A_{2j},A_{2j+1}), .y = packed(B_{2j},B_{2j+1})
    float      C[Kn];
};

__device__ __forceinline__ void load_params_smem(EStepSmem* sp, int b, int tid) {
    if (tid < Kn * 11) {
        int k = tid / 11, q = tid - k * 11;
        float4 v = g_params4[(b * Kn + k) * 11 + q];
        if (q < 10) {
            ulonglong2 w;
            w.x = pk2(v.x, v.y);
            w.y = pk2(v.z, v.w);
            sp->AB[k][q] = w;
        } else {
            sp->C[k] = v.x;
        }
    }
}

__device__ __forceinline__ void loglik_softmax(const EStepSmem* sp, const ull* x2,
                                               float* l, float* p) {
#pragma unroll
    for (int k = 0; k < Kn; k++) {
        ull acc = 0ULL;   // (+0.0f, +0.0f)
#pragma unroll
        for (int j = 0; j < 10; j++) {
            ulonglong2 ab = sp->AB[k][j];
            acc = fma2(fma2(ab.x, x2[j], ab.y), x2[j], acc);  // x*(A*x+B) per lane
        }
        float lo, hi; up2(acc, lo, hi);
        l[k] = sp->C[k] + lo + hi;
    }
    float m = l[0];
#pragma unroll
    for (int k = 1; k < Kn; k++) m = fmaxf(m, l[k]);
    float s = 0.0f;
#pragma unroll
    for (int k = 0; k < Kn; k++) { p[k] = __expf(l[k] - m); s += p[k]; }
    float inv = __fdividef(1.0f, s);
#pragma unroll
    for (int k = 0; k < Kn; k++) p[k] *= inv;
}

// ---------------------------------------------------------------- accumulate (E-step + partial M-step sums)
__launch_bounds__(TILE)
__global__ void accum_kernel(const float* __restrict__ data) {
    __shared__ EStepSmem sp;
    __shared__ __align__(16) float sP[Kn][TILE];   // posteriors transposed [k][t]
    __shared__ float sred[8 * 210];

    const int tid  = threadIdx.x;
    const int b    = blockIdx.y;
    const int wid  = tid >> 5;
    const int lane = tid & 31;

    load_params_smem(&sp, b, tid);

    ull Sx2[Kn]  = {0, 0, 0, 0, 0};   // f32x2: lo = even points, hi = odd points
    ull Sxx2[Kn] = {0, 0, 0, 0, 0};
    const ull ONE2 = pk2(1.0f, 1.0f);
    const float* dbase = data + (size_t)b * Nn * Fn;

    for (int tile = blockIdx.x; tile < NTILES; tile += GRIDX) {
        const int base   = tile * TILE;
        const int nvalid = min(TILE, Nn - base);

        __syncthreads();   // sP safe to overwrite

        // -------- phase 1: per-thread point -> posterior into sP
        if (tid < nvalid) {
            const ulonglong2* xp =
                reinterpret_cast<const ulonglong2*>(dbase + (size_t)(base + tid) * Fn);
            ull x2[10];
#pragma unroll
            for (int j = 0; j < 5; j++) {
                ulonglong2 v = __ldg(xp + j);
                x2[2 * j]     = v.x;
                x2[2 * j + 1] = v.y;
            }
            float l[Kn], p[Kn];
            loglik_softmax(&sp, x2, l, p);
#pragma unroll
            for (int k = 0; k < Kn; k++) sP[k][tid] = p[k];
        }
        __syncthreads();

        // -------- phase 2: warp owns 32 points (2 at a time via f32x2), lane owns feature f
        const int t0w = wid * 32;
        int rem = nvalid - t0w;
        int cnt = rem < 0 ? 0 : (rem > 32 ? 32 : rem);
        const bool act = lane < 20;
        const float* xr = dbase + (size_t)(base + t0w) * Fn + (act ? lane : 0);

        if (cnt == 32) {
#pragma unroll
            for (int i = 0; i < 32; i += 2) {
                float xa = xr[i * Fn];            // L1 hit (loaded by phase 1)
                float xb = xr[i * Fn + Fn];
                ull x2p = act ? pk2(xa, xb) : ONE2;
                ull xx2 = mul2(x2p, x2p);
#pragma unroll
                for (int k = 0; k < Kn; k++) {
                    ull p2 = *reinterpret_cast<const ull*>(&sP[k][t0w + i]);  // broadcast LDS.64
                    Sx2[k]  = fma2(p2, x2p, Sx2[k]);
                    Sxx2[k] = fma2(p2, xx2, Sxx2[k]);
                }
            }
        } else if (cnt > 0) {
            int i = 0;
            for (; i + 1 < cnt; i += 2) {
                float xa = xr[i * Fn];
                float xb = xr[i * Fn + Fn];
                ull x2p = act ? pk2(xa, xb) : ONE2;
                ull xx2 = mul2(x2p, x2p);
#pragma unroll
                for (int k = 0; k < Kn; k++) {
                    ull p2 = *reinterpret_cast<const ull*>(&sP[k][t0w + i]);
                    Sx2[k]  = fma2(p2, x2p, Sx2[k]);
                    Sxx2[k] = fma2(p2, xx2, Sxx2[k]);
                }
            }
            if (i < cnt) {   // odd tail
                float xa = xr[i * Fn];
                ull x2p = act ? pk2(xa, 0.0f) : pk2(1.0f, 0.0f);
                ull xx2 = mul2(x2p, x2p);
#pragma unroll
                for (int k = 0; k < Kn; k++) {
                    ull p2 = pk2(sP[k][t0w + i], 0.0f);
                    Sx2[k]  = fma2(p2, x2p, Sx2[k]);
                    Sxx2[k] = fma2(p2, xx2, Sxx2[k]);
                }
            }
        }
    }

    // -------- block reduction + one atomicAdd per entry
    __syncthreads();
    if (lane < 21) {   // lane 20 carries the Sigma-p (ones-feature) column
#pragma unroll
        for (int k = 0; k < Kn; k++) {
            float lo, hi; up2(Sx2[k], lo, hi);
            sred[wid * 210 + k * 21 + lane] = lo + hi;
        }
#pragma unroll
        for (int k = 0; k < Kn; k++) {
            float lo, hi; up2(Sxx2[k], lo, hi);
            sred[wid * 210 + 105 + k * 21 + lane] = lo + hi;
        }
    }
    __syncthreads();
    if (tid < 210) {
        float v = 0.0f;
#pragma unroll
        for (int w = 0; w < 8; w++) v += sred[w * 210 + tid];
        atomicAdd(&g_acc[b * 210 + tid], v);
    }
}

// ---------------------------------------------------------------- M-step finalize (+ param refresh, + output on last iter)
__global__ void finalize_kernel(int is_last, float* __restrict__ out_means,
                                float* __restrict__ out_var, float* __restrict__ out_pi) {
    int tid = threadIdx.x;
    __shared__ float sS[Bn * Kn];
    if (tid < Bn * Kn) {
        int b = tid / Kn, k = tid - b * Kn;
        sS[tid] = g_acc[b * 210 + k * 21 + 20];
    }
    __syncthreads();
    if (tid < Bn * Kn) {
        int b = tid / Kn, k = tid - b * Kn;
        float S = sS[tid];
        float sum = sS[b * Kn + 0] + sS[b * Kn + 1] + sS[b * Kn + 2] +
                    sS[b * Kn + 3] + sS[b * Kn + 4];
        // pi = (S/N) / max(sum|S|/N, 1e-12) == S / max(sum, N*1e-12)
        float pi = S / fmaxf(sum, (float)Nn * 1e-12f);
        float dS = S + 1e-7f;
        float invdS = 1.0f / dS;

        float mu[Fn], vv[Fn];
#pragma unroll
        for (int f = 0; f < Fn; f++) {
            float sx  = g_acc[b * 210 + k * 21 + f];
            float sxx = g_acc[b * 210 + 105 + k * 21 + f];
            float m = sx * invdS;
            float v = (sxx - 2.0f * m * sx + m * m * S) * invdS + 1e-6f;  // var + EPS_VAR
            mu[f] = m;
            vv[f] = v;
        }
        write_params(b, k, logf(pi), mu, vv);
        if (is_last) {
#pragma unroll
            for (int f = 0; f < Fn; f++) {
                out_means[(b * Kn + k) * Fn + f] = mu[f];
                out_var[(b * Kn + k) * Fn + f]   = vv[f];
            }
            out_pi[b * Kn + k] = pi;
        }
    }
    __syncthreads();
    for (int i = tid; i < Bn * 210; i += blockDim.x) g_acc[i] = 0.0f;
}

// ---------------------------------------------------------------- final E-step: write ll + post [B,N,K]
__launch_bounds__(TILE)
__global__ void estep_out_kernel(const float* __restrict__ data,
                                 float* __restrict__ out_ll,
                                 float* __restrict__ out_post) {
    __shared__ EStepSmem sp;
    const int tid = threadIdx.x;
    const int b   = blockIdx.y;
    load_params_smem(&sp, b, tid);
    __syncthreads();

    int n = blockIdx.x * TILE + tid;
    if (n < Nn) {
        const ulonglong2* xp =
            reinterpret_cast<const ulonglong2*>(data + ((size_t)b * Nn + n) * Fn);
        ull x2[10];
#pragma unroll
        for (int j = 0; j < 5; j++) {
            ulonglong2 v = __ldg(xp + j);
            x2[2 * j]     = v.x;
            x2[2 * j + 1] = v.y;
        }
        float l[Kn], p[Kn];
        loglik_softmax(&sp, x2, l, p);

        size_t o = ((size_t)b * Nn + n) * Kn;
#pragma unroll
        for (int k = 0; k < Kn; k++) out_ll[o + k] = l[k];
#pragma unroll
        for (int k = 0; k < Kn; k++) out_post[o + k] = p[k];
    }
}

// ---------------------------------------------------------------- launch
extern "C" void kernel_launch(void* const* d_in, const int* in_sizes, int n_in,
                              void* d_out, int out_size) {
    const float* data  = (const float*)d_in[0];
    const float* means = (const float*)d_in[1];
    const float* var   = (const float*)d_in[2];
    const float* pri   = (const float*)d_in[3];

    float* out = (float*)d_out;
    size_t NK = (size_t)Bn * Nn * Kn;                 // 3,200,000
    float* out_ll    = out;
    float* out_post  = out + NK;
    float* out_means = out + 2 * NK;
    float* out_var   = out_means + Bn * Kn * Fn;      // +800
    float* out_pi    = out_var   + Bn * Kn * Fn;      // +800

    init_kernel<<<1, 256>>>(means, var, pri);
    for (int it = 0; it < NITER; it++) {
        accum_kernel<<<dim3(GRIDX, Bn), TILE>>>(data);
        finalize_kernel<<<1, 256>>>(it == NITER - 1 ? 1 : 0, out_means, out_var, out_pi);
    }
    estep_out_kernel<<<dim3(NTILES, Bn), TILE>>>(data, out_ll, out_post);
}